// round 1
// baseline (speedup 1.0000x reference)
#include <cuda_runtime.h>
#include <math.h>

#define BB 8
#define HWN 4096

// -------- scratch (allocation-free rule: __device__ globals) --------
__device__ float g_Q [BB*HWN*64];   // [b][p][ci]
__device__ float g_K [BB*HWN*64];
__device__ float g_V [BB*HWN*64];
__device__ float g_AO[BB*HWN*64];   // attention output [b][p][d]
__device__ float g_SW[BB*128*HWN];  // sigmoid gates [b][ci][p]

// ===================================================================
// Kernel 1: fused gf-build (upsample+concat) + QKV 1x1 convs
// grid (64 rows, B), 256 threads
// ===================================================================
__global__ void qkv_kernel(const float* __restrict__ x1, const float* __restrict__ x2,
                           const float* __restrict__ x3, const float* __restrict__ x4,
                           const float* __restrict__ qw, const float* __restrict__ qb,
                           const float* __restrict__ kw, const float* __restrict__ kb,
                           const float* __restrict__ vw, const float* __restrict__ vb) {
  extern __shared__ float sh[];
  float* wst  = sh;                    // [128][192] transposed weights (q|k|v)
  float* gfs  = wst + 128*192;         // [128][68]  channel-major gf row tile
  float* bias = gfs + 128*68;          // [192]
  float* outs = bias + 192;            // [192][65]  output staging (padded)
  const int b = blockIdx.y, y = blockIdx.x, tid = threadIdx.x;

  for (int i = tid; i < 64*128; i += 256) {
    int ci = i >> 7, c = i & 127;
    wst[c*192 + ci]       = qw[i];
    wst[c*192 + 64 + ci]  = kw[i];
    wst[c*192 + 128 + ci] = vw[i];
  }
  for (int i = tid; i < 192; i += 256)
    bias[i] = (i < 64) ? qb[i] : (i < 128 ? kb[i-64] : vb[i-128]);

  // channels 0..31: copy x1 row
  for (int i = tid; i < 32*64; i += 256) {
    int c = i >> 6, x = i & 63;
    gfs[c*68 + x] = x1[((b*32 + c)*64 + y)*64 + x];
  }
  // channels 32.., bilinear align-corners upsample of x2/x3/x4
  const float* srcs[3] = {x2, x3, x4};
  const int    Hs[3]   = {32, 16, 8};
  #pragma unroll
  for (int lvl = 0; lvl < 3; lvl++) {
    const int H = Hs[lvl];
    const float* src = srcs[lvl];
    float fy = (float)y * (float)(H-1) / 63.0f;
    int y0 = (int)fy; if (y0 > H-1) y0 = H-1;
    int y1i = min(y0+1, H-1);
    float wy = fy - (float)y0;
    for (int i = tid; i < 32*64; i += 256) {
      int c = i >> 6, x = i & 63;
      float fx = (float)x * (float)(H-1) / 63.0f;
      int x0 = (int)fx; if (x0 > H-1) x0 = H-1;
      int x1i = min(x0+1, H-1);
      float wx = fx - (float)x0;
      const float* r0 = src + ((b*32 + c)*H + y0)*H;
      const float* r1 = src + ((b*32 + c)*H + y1i)*H;
      float top = r0[x0]*(1.f-wx) + r0[x1i]*wx;
      float bot = r1[x0]*(1.f-wx) + r1[x1i]*wx;
      gfs[(32*(lvl+1) + c)*68 + x] = top*(1.f-wy) + bot*wy;
    }
  }
  __syncthreads();

  // register-tiled GEMM: 192 out-rows x 64 positions, K=128
  const int tx = tid & 15, ty = tid >> 4;
  float acc[12][4];
  #pragma unroll
  for (int i = 0; i < 12; i++) { acc[i][0]=acc[i][1]=acc[i][2]=acc[i][3]=0.f; }
  for (int c = 0; c < 128; c++) {
    float4 g = *(const float4*)&gfs[c*68 + tx*4];
    const float* wr = &wst[c*192 + ty*12];
    float4 w0 = *(const float4*)&wr[0];
    float4 w1 = *(const float4*)&wr[4];
    float4 w2 = *(const float4*)&wr[8];
    float wv[12] = {w0.x,w0.y,w0.z,w0.w, w1.x,w1.y,w1.z,w1.w, w2.x,w2.y,w2.z,w2.w};
    #pragma unroll
    for (int i = 0; i < 12; i++) {
      acc[i][0] += wv[i]*g.x; acc[i][1] += wv[i]*g.y;
      acc[i][2] += wv[i]*g.z; acc[i][3] += wv[i]*g.w;
    }
  }
  #pragma unroll
  for (int i = 0; i < 12; i++) {
    int row = ty*12 + i;
    float bbv = bias[row];
    #pragma unroll
    for (int j = 0; j < 4; j++)
      outs[row*65 + tx*4 + j] = acc[i][j] + bbv;
  }
  __syncthreads();
  // coalesced writeout: [b][p][ci]
  int pbase = (b*HWN + y*64);
  for (int i = tid; i < 4096; i += 256) {
    int p = i >> 6, ci = i & 63;
    g_Q[pbase*64 + i] = outs[ci*65 + p];
    g_K[pbase*64 + i] = outs[(64+ci)*65 + p];
    g_V[pbase*64 + i] = outs[(128+ci)*65 + p];
  }
}

// ===================================================================
// Kernel 2: flash attention, fp32, head-dim 64, seq 4096, no scale
// grid (64 q-tiles, B), 256 threads, BM=BN=64
// ===================================================================
__global__ void attn_kernel() {
  extern __shared__ float sh[];
  float* Qst = sh;             // [64 d][68]: Qst[d][r]
  float* Kst = Qst + 64*68;    // [64 d][68]: Kst[d][c]
  float* Vs  = Kst + 64*68;    // [64 j][68]: Vs[j][dd]
  float* Pst = Vs  + 64*68;    // [64 j][68]: Pst[j][r]
  const int b = blockIdx.y, m0 = blockIdx.x*64;
  const int tid = threadIdx.x, tx = tid & 15, ty = tid >> 4;

  const float* Qg = g_Q + (b*HWN + m0)*64;
  for (int i = tid; i < 4096; i += 256) { int r = i>>6, d = i&63; Qst[d*68 + r] = Qg[i]; }

  float m_i[4] = {-1e30f,-1e30f,-1e30f,-1e30f};
  float l_i[4] = {0.f,0.f,0.f,0.f};
  float acc[4][4] = {};

  for (int jt = 0; jt < 64; jt++) {
    __syncthreads();   // previous PV-GEMM done before overwriting K/V
    const float* Kg = g_K + (b*HWN + jt*64)*64;
    const float* Vg = g_V + (b*HWN + jt*64)*64;
    for (int i = tid; i < 4096; i += 256) {
      int r = i>>6, d = i&63;
      Kst[d*68 + r] = Kg[i];
      Vs [r*68 + d] = Vg[i];
    }
    __syncthreads();

    // S = Q K^T (64x64), 4x4 micro-tile per thread
    float s[4][4] = {};
    #pragma unroll 8
    for (int d = 0; d < 64; d++) {
      float4 a = *(const float4*)&Qst[d*68 + ty*4];
      float4 k = *(const float4*)&Kst[d*68 + tx*4];
      s[0][0]+=a.x*k.x; s[0][1]+=a.x*k.y; s[0][2]+=a.x*k.z; s[0][3]+=a.x*k.w;
      s[1][0]+=a.y*k.x; s[1][1]+=a.y*k.y; s[1][2]+=a.y*k.z; s[1][3]+=a.y*k.w;
      s[2][0]+=a.z*k.x; s[2][1]+=a.z*k.y; s[2][2]+=a.z*k.z; s[2][3]+=a.z*k.w;
      s[3][0]+=a.w*k.x; s[3][1]+=a.w*k.y; s[3][2]+=a.w*k.z; s[3][3]+=a.w*k.w;
    }

    // online softmax (rows span the 16 tx-lanes; butterfly within 16-lane half-warp)
    #pragma unroll
    for (int i = 0; i < 4; i++) {
      float mx = fmaxf(fmaxf(s[i][0], s[i][1]), fmaxf(s[i][2], s[i][3]));
      #pragma unroll
      for (int mk = 1; mk < 16; mk <<= 1)
        mx = fmaxf(mx, __shfl_xor_sync(0xffffffffu, mx, mk));
      float mnew = fmaxf(m_i[i], mx);
      float corr = __expf(m_i[i] - mnew);
      float rs = 0.f;
      #pragma unroll
      for (int j = 0; j < 4; j++) { float p = __expf(s[i][j] - mnew); s[i][j] = p; rs += p; }
      #pragma unroll
      for (int mk = 1; mk < 16; mk <<= 1)
        rs += __shfl_xor_sync(0xffffffffu, rs, mk);
      l_i[i] = l_i[i]*corr + rs;
      m_i[i] = mnew;
      #pragma unroll
      for (int dd = 0; dd < 4; dd++) acc[i][dd] *= corr;
      #pragma unroll
      for (int j = 0; j < 4; j++) Pst[(tx*4 + j)*68 + ty*4 + i] = s[i][j];
    }
    __syncthreads();

    // O += P V (64x64x64)
    #pragma unroll 8
    for (int j = 0; j < 64; j++) {
      float4 p = *(const float4*)&Pst[j*68 + ty*4];
      float4 v = *(const float4*)&Vs [j*68 + tx*4];
      acc[0][0]+=p.x*v.x; acc[0][1]+=p.x*v.y; acc[0][2]+=p.x*v.z; acc[0][3]+=p.x*v.w;
      acc[1][0]+=p.y*v.x; acc[1][1]+=p.y*v.y; acc[1][2]+=p.y*v.z; acc[1][3]+=p.y*v.w;
      acc[2][0]+=p.z*v.x; acc[2][1]+=p.z*v.y; acc[2][2]+=p.z*v.z; acc[2][3]+=p.z*v.w;
      acc[3][0]+=p.w*v.x; acc[3][1]+=p.w*v.y; acc[3][2]+=p.w*v.z; acc[3][3]+=p.w*v.w;
    }
  }

  float* AOg = g_AO + (b*HWN + m0)*64;
  #pragma unroll
  for (int i = 0; i < 4; i++) {
    float inv = 1.f / l_i[i];
    float4 o = make_float4(acc[i][0]*inv, acc[i][1]*inv, acc[i][2]*inv, acc[i][3]*inv);
    *(float4*)&AOg[(ty*4 + i)*64 + tx*4] = o;
  }
}

// ===================================================================
// Kernel 3: out-proj + gate MLP + sigmoid  (attn_out -> g_SW)
// grid (256 pos-tiles of 16, B), 256 threads
// ===================================================================
__global__ void proj_kernel(const float* __restrict__ ow_, const float* __restrict__ ob,
                            const float* __restrict__ g1w, const float* __restrict__ g1b,
                            const float* __restrict__ g2w, const float* __restrict__ g2b) {
  extern __shared__ float sh[];
  float* owt  = sh;              // [64][128]
  float* g1wt = owt + 8192;      // [128][32]
  float* g2wt = g1wt + 4096;     // [32][128]
  float* obs  = g2wt + 4096;     // 128
  float* g1bs = obs + 128;       // 32
  float* g2bs = g1bs + 32;       // 128
  float* ao   = g2bs + 128;      // [16][64]
  float* gf2  = ao + 1024;       // [16][128]
  float* hb   = gf2 + 2048;      // [16][32]
  float* swt  = hb + 512;        // [128][16]
  const int b = blockIdx.y, p0 = blockIdx.x*16, tid = threadIdx.x;

  for (int i = tid; i < 8192; i += 256) { int ci = i>>6, d = i&63;  owt [d*128+ci] = ow_[i]; }
  for (int i = tid; i < 4096; i += 256) { int co = i>>7, c = i&127; g1wt[c*32 +co] = g1w[i]; }
  for (int i = tid; i < 4096; i += 256) { int ci = i>>5, c = i&31;  g2wt[c*128+ci] = g2w[i]; }
  for (int i = tid; i < 128;  i += 256) obs[i]  = ob[i];
  for (int i = tid; i < 32;   i += 256) g1bs[i] = g1b[i];
  for (int i = tid; i < 128;  i += 256) g2bs[i] = g2b[i];
  const float* AOg = g_AO + (b*HWN + p0)*64;
  for (int i = tid; i < 1024; i += 256) ao[i] = AOg[i];
  __syncthreads();

  for (int o = tid; o < 2048; o += 256) {           // gf2 = ow_ @ ao + ob
    int p = o >> 7, ci = o & 127;
    float s = obs[ci];
    const float* av = &ao[p*64];
    #pragma unroll 8
    for (int d = 0; d < 64; d++) s += owt[d*128+ci]*av[d];
    gf2[o] = s;
  }
  __syncthreads();
  for (int o = tid; o < 512; o += 256) {            // h = relu(g1w @ gf2 + g1b)
    int p = o >> 5, co = o & 31;
    float s = g1bs[co];
    const float* gv = &gf2[p*128];
    #pragma unroll 8
    for (int c = 0; c < 128; c++) s += g1wt[c*32+co]*gv[c];
    hb[o] = fmaxf(s, 0.f);
  }
  __syncthreads();
  for (int o = tid; o < 2048; o += 256) {           // sw = sigmoid(g2w @ h + g2b)
    int p = o >> 7, ci = o & 127;
    float s = g2bs[ci];
    const float* hv = &hb[p*32];
    #pragma unroll
    for (int c = 0; c < 32; c++) s += g2wt[c*128+ci]*hv[c];
    swt[ci*16 + p] = 1.f/(1.f + __expf(-s));
  }
  __syncthreads();
  for (int o = tid; o < 2048; o += 256) {           // coalesced-ish channel-major store
    int ci = o >> 4, pp = o & 15;
    g_SW[(b*128+ci)*HWN + p0 + pp] = swt[o];
  }
}

// ===================================================================
// Kernel 4: final gating (with bilinear resample of gates for x2..x4)
// ===================================================================
__device__ __forceinline__ float sample_sw(const float* __restrict__ plane, int y, int x, int OH) {
  float fy = (float)y * 63.0f / (float)(OH-1);
  float fx = (float)x * 63.0f / (float)(OH-1);
  int y0 = (int)fy; if (y0 > 63) y0 = 63;
  int x0 = (int)fx; if (x0 > 63) x0 = 63;
  int y1 = min(y0+1, 63), x1 = min(x0+1, 63);
  float wy = fy - (float)y0, wx = fx - (float)x0;
  float a = plane[y0*64+x0], bv = plane[y0*64+x1];
  float c = plane[y1*64+x0], d = plane[y1*64+x1];
  return (a*(1.f-wx)+bv*wx)*(1.f-wy) + (c*(1.f-wx)+d*wx)*wy;
}

__global__ void gate_kernel(const float* __restrict__ x1, const float* __restrict__ x2,
                            const float* __restrict__ x3, const float* __restrict__ x4,
                            float* __restrict__ out) {
  int idx = blockIdx.x*256 + threadIdx.x;
  const int N1 = BB*32*4096, N2 = BB*32*1024, N3 = BB*32*256, N4 = BB*32*64;
  if (idx < N1) {
    int b = idx >> 17, c = (idx >> 12) & 31, p = idx & 4095;
    out[idx] = x1[idx]*(1.f + g_SW[(b*128 + c)*HWN + p]);
  } else if (idx < N1+N2) {
    int i = idx - N1;
    int b = i >> 15, c = (i >> 10) & 31, y = (i >> 5) & 31, x = i & 31;
    const float* plane = g_SW + (b*128 + 32 + c)*HWN;
    out[idx] = x2[i]*(1.f + sample_sw(plane, y, x, 32));
  } else if (idx < N1+N2+N3) {
    int i = idx - N1 - N2;
    int b = i >> 13, c = (i >> 8) & 31, y = (i >> 4) & 15, x = i & 15;
    const float* plane = g_SW + (b*128 + 64 + c)*HWN;
    out[idx] = x3[i]*(1.f + sample_sw(plane, y, x, 16));
  } else if (idx < N1+N2+N3+N4) {
    int i = idx - N1 - N2 - N3;
    int b = i >> 11, c = (i >> 6) & 31, y = (i >> 3) & 7, x = i & 7;
    const float* plane = g_SW + (b*128 + 96 + c)*HWN;
    out[idx] = x4[i]*(1.f + sample_sw(plane, y, x, 8));
  }
}

// ===================================================================
extern "C" void kernel_launch(void* const* d_in, const int* in_sizes, int n_in,
                              void* d_out, int out_size) {
  const float* x1  = (const float*)d_in[0];
  const float* x2  = (const float*)d_in[1];
  const float* x3  = (const float*)d_in[2];
  const float* x4  = (const float*)d_in[3];
  const float* qw  = (const float*)d_in[4];
  const float* qb  = (const float*)d_in[5];
  const float* kw  = (const float*)d_in[6];
  const float* kb  = (const float*)d_in[7];
  const float* vw  = (const float*)d_in[8];
  const float* vb  = (const float*)d_in[9];
  const float* ow_ = (const float*)d_in[10];
  const float* ob  = (const float*)d_in[11];
  const float* g1w = (const float*)d_in[12];
  const float* g1b = (const float*)d_in[13];
  const float* g2w = (const float*)d_in[14];
  const float* g2b = (const float*)d_in[15];
  float* out = (float*)d_out;

  const int QKV_SMEM  = (128*192 + 128*68 + 192 + 192*65) * 4;  // 183808 B
  const int ATTN_SMEM = 4*64*68*4;                              // 69632 B
  const int PROJ_SMEM = (8192+4096+4096+128+32+128+1024+2048+512+2048) * 4; // 89216 B

  cudaFuncSetAttribute(qkv_kernel,  cudaFuncAttributeMaxDynamicSharedMemorySize, QKV_SMEM);
  cudaFuncSetAttribute(attn_kernel, cudaFuncAttributeMaxDynamicSharedMemorySize, ATTN_SMEM);
  cudaFuncSetAttribute(proj_kernel, cudaFuncAttributeMaxDynamicSharedMemorySize, PROJ_SMEM);

  qkv_kernel <<<dim3(64, BB),  256, QKV_SMEM >>>(x1, x2, x3, x4, qw, qb, kw, kb, vw, vb);
  attn_kernel<<<dim3(64, BB),  256, ATTN_SMEM>>>();
  proj_kernel<<<dim3(256, BB), 256, PROJ_SMEM>>>(ow_, ob, g1w, g1b, g2w, g2b);

  const int TOTAL = BB*32*(4096 + 1024 + 256 + 64);  // 1392640
  gate_kernel<<<(TOTAL + 255)/256, 256>>>(x1, x2, x3, x4, out);
}

// round 2
// speedup vs baseline: 2.4984x; 2.4984x over previous
#include <cuda_runtime.h>
#include <math.h>
#include <stdint.h>

#define BB 8
#define HWN 4096

// -------- scratch (allocation-free rule: __device__ globals) --------
__device__ float g_Q [BB*HWN*64];   // [b][p][ci]  (tf32-rounded)
__device__ float g_K [BB*HWN*64];   // (tf32-rounded)
__device__ float g_V [BB*HWN*64];   // (tf32-rounded)
__device__ float g_AO[BB*HWN*64];   // attention output [b][p][d]
__device__ float g_SW[BB*128*HWN];  // sigmoid gates [b][ci][p]

__device__ __forceinline__ float tf32r(float x) {
  uint32_t u;
  asm("cvt.rna.tf32.f32 %0, %1;" : "=r"(u) : "f"(x));
  return __uint_as_float(u);
}

// ===================================================================
// Kernel 1: fused gf-build (upsample+concat) + QKV 1x1 convs
// grid (64 rows, B), 256 threads
// ===================================================================
__global__ void qkv_kernel(const float* __restrict__ x1, const float* __restrict__ x2,
                           const float* __restrict__ x3, const float* __restrict__ x4,
                           const float* __restrict__ qw, const float* __restrict__ qb,
                           const float* __restrict__ kw, const float* __restrict__ kb,
                           const float* __restrict__ vw, const float* __restrict__ vb) {
  extern __shared__ float sh[];
  float* wst  = sh;                    // [128][192] transposed weights (q|k|v)
  float* gfs  = wst + 128*192;         // [128][68]  channel-major gf row tile
  float* bias = gfs + 128*68;          // [192]
  float* outs = bias + 192;            // [192][65]  output staging (padded)
  const int b = blockIdx.y, y = blockIdx.x, tid = threadIdx.x;

  for (int i = tid; i < 64*128; i += 256) {
    int ci = i >> 7, c = i & 127;
    wst[c*192 + ci]       = qw[i];
    wst[c*192 + 64 + ci]  = kw[i];
    wst[c*192 + 128 + ci] = vw[i];
  }
  for (int i = tid; i < 192; i += 256)
    bias[i] = (i < 64) ? qb[i] : (i < 128 ? kb[i-64] : vb[i-128]);

  for (int i = tid; i < 32*64; i += 256) {
    int c = i >> 6, x = i & 63;
    gfs[c*68 + x] = x1[((b*32 + c)*64 + y)*64 + x];
  }
  const float* srcs[3] = {x2, x3, x4};
  const int    Hs[3]   = {32, 16, 8};
  #pragma unroll
  for (int lvl = 0; lvl < 3; lvl++) {
    const int H = Hs[lvl];
    const float* src = srcs[lvl];
    float fy = (float)y * (float)(H-1) / 63.0f;
    int y0 = (int)fy; if (y0 > H-1) y0 = H-1;
    int y1i = min(y0+1, H-1);
    float wy = fy - (float)y0;
    for (int i = tid; i < 32*64; i += 256) {
      int c = i >> 6, x = i & 63;
      float fx = (float)x * (float)(H-1) / 63.0f;
      int x0 = (int)fx; if (x0 > H-1) x0 = H-1;
      int x1i = min(x0+1, H-1);
      float wx = fx - (float)x0;
      const float* r0 = src + ((b*32 + c)*H + y0)*H;
      const float* r1 = src + ((b*32 + c)*H + y1i)*H;
      float top = r0[x0]*(1.f-wx) + r0[x1i]*wx;
      float bot = r1[x0]*(1.f-wx) + r1[x1i]*wx;
      gfs[(32*(lvl+1) + c)*68 + x] = top*(1.f-wy) + bot*wy;
    }
  }
  __syncthreads();

  const int tx = tid & 15, ty = tid >> 4;
  float acc[12][4];
  #pragma unroll
  for (int i = 0; i < 12; i++) { acc[i][0]=acc[i][1]=acc[i][2]=acc[i][3]=0.f; }
  for (int c = 0; c < 128; c++) {
    float4 g = *(const float4*)&gfs[c*68 + tx*4];
    const float* wr = &wst[c*192 + ty*12];
    float4 w0 = *(const float4*)&wr[0];
    float4 w1 = *(const float4*)&wr[4];
    float4 w2 = *(const float4*)&wr[8];
    float wv[12] = {w0.x,w0.y,w0.z,w0.w, w1.x,w1.y,w1.z,w1.w, w2.x,w2.y,w2.z,w2.w};
    #pragma unroll
    for (int i = 0; i < 12; i++) {
      acc[i][0] += wv[i]*g.x; acc[i][1] += wv[i]*g.y;
      acc[i][2] += wv[i]*g.z; acc[i][3] += wv[i]*g.w;
    }
  }
  #pragma unroll
  for (int i = 0; i < 12; i++) {
    int row = ty*12 + i;
    float bbv = bias[row];
    #pragma unroll
    for (int j = 0; j < 4; j++)
      outs[row*65 + tx*4 + j] = acc[i][j] + bbv;
  }
  __syncthreads();
  // coalesced writeout, tf32-rounded so the attention kernel needs no cvt
  int pbase = (b*HWN + y*64);
  for (int i = tid; i < 4096; i += 256) {
    int p = i >> 6, ci = i & 63;
    g_Q[pbase*64 + i] = tf32r(outs[ci*65 + p]);
    g_K[pbase*64 + i] = tf32r(outs[(64+ci)*65 + p]);
    g_V[pbase*64 + i] = tf32r(outs[(128+ci)*65 + p]);
  }
}

// ===================================================================
// Kernel 2: tensor-core flash attention (tf32 HMMA), d=64, seq=4096
// grid (32 q-tiles of 128, B), 256 threads (8 warps x 16 rows)
// ===================================================================
#define KST 68
#define VST 72
#define STAGEF (64*KST + 64*VST)

__device__ __forceinline__ void cp_async16(uint32_t smem_dst, const void* gsrc) {
  asm volatile("cp.async.ca.shared.global [%0], [%1], 16;\n"
               :: "r"(smem_dst), "l"(gsrc));
}

__device__ __forceinline__ void mma_tf32(float d[4], const uint32_t a[4],
                                         uint32_t b0, uint32_t b1) {
  asm volatile("mma.sync.aligned.m16n8k8.row.col.f32.tf32.tf32.f32 "
               "{%0,%1,%2,%3}, {%4,%5,%6,%7}, {%8,%9}, {%0,%1,%2,%3};"
               : "+f"(d[0]), "+f"(d[1]), "+f"(d[2]), "+f"(d[3])
               : "r"(a[0]), "r"(a[1]), "r"(a[2]), "r"(a[3]), "r"(b0), "r"(b1));
}

__device__ __forceinline__ void prefetch_kv(uint32_t sbase, int b, int jt, int stage, int tid) {
  uint32_t st = sbase + (uint32_t)stage * (STAGEF*4);
  const float* Ksrc = g_K + ((size_t)b*HWN + jt*64)*64;
  const float* Vsrc = g_V + ((size_t)b*HWN + jt*64)*64;
  #pragma unroll
  for (int k = 0; k < 8; k++) {
    int i = tid + k*256;            // 0..2047
    int r = (i >> 4) & 63, q = i & 15;
    if (i < 1024) cp_async16(st + (uint32_t)(r*KST + q*4)*4,          Ksrc + r*64 + q*4);
    else          cp_async16(st + (uint32_t)(64*KST + r*VST + q*4)*4, Vsrc + r*64 + q*4);
  }
}

__global__ void __launch_bounds__(256) attn_kernel() {
  extern __shared__ float sh[];
  uint32_t sbase = (uint32_t)__cvta_generic_to_shared(sh);
  const int b = blockIdx.y, m0 = blockIdx.x*128;
  const int tid = threadIdx.x, w = tid >> 5, lane = tid & 31;
  const int g = lane >> 2, t = lane & 3;

  // Q fragments, resident in registers (already tf32-rounded in gmem)
  const float* Qg = g_Q + ((size_t)b*HWN + m0 + w*16)*64;
  uint32_t qa[8][4];
  #pragma unroll
  for (int kt = 0; kt < 8; kt++) {
    qa[kt][0] = __float_as_uint(Qg[ g   *64 + kt*8 + t    ]);
    qa[kt][1] = __float_as_uint(Qg[(g+8)*64 + kt*8 + t    ]);
    qa[kt][2] = __float_as_uint(Qg[ g   *64 + kt*8 + t + 4]);
    qa[kt][3] = __float_as_uint(Qg[(g+8)*64 + kt*8 + t + 4]);
  }

  float m0r = -1e30f, m1r = -1e30f, l0 = 0.f, l1 = 0.f;
  float o[8][4] = {};

  prefetch_kv(sbase, b, 0, 0, tid);
  asm volatile("cp.async.commit_group;\n" ::: "memory");

  for (int jt = 0; jt < 64; jt++) {
    if (jt + 1 < 64) {
      prefetch_kv(sbase, b, jt+1, (jt+1)&1, tid);
      asm volatile("cp.async.commit_group;\n" ::: "memory");
      asm volatile("cp.async.wait_group 1;\n" ::: "memory");
    } else {
      asm volatile("cp.async.wait_group 0;\n" ::: "memory");
    }
    __syncthreads();

    const float* Kst = sh + (jt&1)*STAGEF;
    const float* Vst = Kst + 64*KST;

    // ---- S = Q K^T (128x64 per CTA, 16x64 per warp) ----
    float s[8][4] = {};
    #pragma unroll
    for (int kt = 0; kt < 8; kt++) {
      #pragma unroll
      for (int nt = 0; nt < 8; nt++) {
        uint32_t b0 = __float_as_uint(Kst[(nt*8 + g)*KST + kt*8 + t    ]);
        uint32_t b1 = __float_as_uint(Kst[(nt*8 + g)*KST + kt*8 + t + 4]);
        mma_tf32(s[nt], qa[kt], b0, b1);
      }
    }

    // ---- online softmax (rows g and g+8 of this warp's strip) ----
    float rmax0 = -1e30f, rmax1 = -1e30f;
    #pragma unroll
    for (int nt = 0; nt < 8; nt++) {
      rmax0 = fmaxf(rmax0, fmaxf(s[nt][0], s[nt][1]));
      rmax1 = fmaxf(rmax1, fmaxf(s[nt][2], s[nt][3]));
    }
    rmax0 = fmaxf(rmax0, __shfl_xor_sync(0xffffffffu, rmax0, 1));
    rmax0 = fmaxf(rmax0, __shfl_xor_sync(0xffffffffu, rmax0, 2));
    rmax1 = fmaxf(rmax1, __shfl_xor_sync(0xffffffffu, rmax1, 1));
    rmax1 = fmaxf(rmax1, __shfl_xor_sync(0xffffffffu, rmax1, 2));
    float mn0 = fmaxf(m0r, rmax0), mn1 = fmaxf(m1r, rmax1);
    float c0 = __expf(m0r - mn0), c1 = __expf(m1r - mn1);
    m0r = mn0; m1r = mn1;
    float rs0 = 0.f, rs1 = 0.f;
    #pragma unroll
    for (int nt = 0; nt < 8; nt++) {
      s[nt][0] = __expf(s[nt][0] - mn0);
      s[nt][1] = __expf(s[nt][1] - mn0);
      s[nt][2] = __expf(s[nt][2] - mn1);
      s[nt][3] = __expf(s[nt][3] - mn1);
      rs0 += s[nt][0] + s[nt][1];
      rs1 += s[nt][2] + s[nt][3];
    }
    rs0 += __shfl_xor_sync(0xffffffffu, rs0, 1);
    rs0 += __shfl_xor_sync(0xffffffffu, rs0, 2);
    rs1 += __shfl_xor_sync(0xffffffffu, rs1, 1);
    rs1 += __shfl_xor_sync(0xffffffffu, rs1, 2);
    l0 = l0*c0 + rs0;  l1 = l1*c1 + rs1;
    #pragma unroll
    for (int nt = 0; nt < 8; nt++) {
      o[nt][0] *= c0; o[nt][1] *= c0; o[nt][2] *= c1; o[nt][3] *= c1;
    }

    // ---- O += P V : relayout P (C-frag -> A-frag) via quad shuffles ----
    const int srcA = (lane & ~3) | (t >> 1);
    const int srcB = srcA + 2;
    #pragma unroll
    for (int kt = 0; kt < 8; kt++) {
      float v00 = __shfl_sync(0xffffffffu, s[kt][0], srcA);
      float v01 = __shfl_sync(0xffffffffu, s[kt][1], srcA);
      float v10 = __shfl_sync(0xffffffffu, s[kt][2], srcA);
      float v11 = __shfl_sync(0xffffffffu, s[kt][3], srcA);
      float v20 = __shfl_sync(0xffffffffu, s[kt][0], srcB);
      float v21 = __shfl_sync(0xffffffffu, s[kt][1], srcB);
      float v30 = __shfl_sync(0xffffffffu, s[kt][2], srcB);
      float v31 = __shfl_sync(0xffffffffu, s[kt][3], srcB);
      uint32_t pa[4];
      pa[0] = __float_as_uint((t & 1) ? v01 : v00);   // P[g   ][8kt+t]
      pa[1] = __float_as_uint((t & 1) ? v11 : v10);   // P[g+8 ][8kt+t]
      pa[2] = __float_as_uint((t & 1) ? v21 : v20);   // P[g   ][8kt+t+4]
      pa[3] = __float_as_uint((t & 1) ? v31 : v30);   // P[g+8 ][8kt+t+4]
      #pragma unroll
      for (int nt = 0; nt < 8; nt++) {
        uint32_t b0 = __float_as_uint(Vst[(kt*8 + t    )*VST + nt*8 + g]);
        uint32_t b1 = __float_as_uint(Vst[(kt*8 + t + 4)*VST + nt*8 + g]);
        mma_tf32(o[nt], pa, b0, b1);
      }
    }
    __syncthreads();   // all reads of this stage done before it is refilled
  }

  float* AO = g_AO + ((size_t)b*HWN + m0 + w*16)*64;
  float i0 = 1.f / l0, i1 = 1.f / l1;
  #pragma unroll
  for (int nt = 0; nt < 8; nt++) {
    *(float2*)&AO[ g   *64 + nt*8 + 2*t] = make_float2(o[nt][0]*i0, o[nt][1]*i0);
    *(float2*)&AO[(g+8)*64 + nt*8 + 2*t] = make_float2(o[nt][2]*i1, o[nt][3]*i1);
  }
}

// ===================================================================
// Kernel 3: out-proj + gate MLP + sigmoid  (attn_out -> g_SW)
// ===================================================================
__global__ void proj_kernel(const float* __restrict__ ow_, const float* __restrict__ ob,
                            const float* __restrict__ g1w, const float* __restrict__ g1b,
                            const float* __restrict__ g2w, const float* __restrict__ g2b) {
  extern __shared__ float sh[];
  float* owt  = sh;              // [64][128]
  float* g1wt = owt + 8192;      // [128][32]
  float* g2wt = g1wt + 4096;     // [32][128]
  float* obs  = g2wt + 4096;     // 128
  float* g1bs = obs + 128;       // 32
  float* g2bs = g1bs + 32;       // 128
  float* ao   = g2bs + 128;      // [16][64]
  float* gf2  = ao + 1024;       // [16][128]
  float* hb   = gf2 + 2048;      // [16][32]
  float* swt  = hb + 512;        // [128][16]
  const int b = blockIdx.y, p0 = blockIdx.x*16, tid = threadIdx.x;

  for (int i = tid; i < 8192; i += 256) { int ci = i>>6, d = i&63;  owt [d*128+ci] = ow_[i]; }
  for (int i = tid; i < 4096; i += 256) { int co = i>>7, c = i&127; g1wt[c*32 +co] = g1w[i]; }
  for (int i = tid; i < 4096; i += 256) { int ci = i>>5, c = i&31;  g2wt[c*128+ci] = g2w[i]; }
  for (int i = tid; i < 128;  i += 256) obs[i]  = ob[i];
  for (int i = tid; i < 32;   i += 256) g1bs[i] = g1b[i];
  for (int i = tid; i < 128;  i += 256) g2bs[i] = g2b[i];
  const float* AOg = g_AO + ((size_t)b*HWN + p0)*64;
  for (int i = tid; i < 1024; i += 256) ao[i] = AOg[i];
  __syncthreads();

  for (int o = tid; o < 2048; o += 256) {
    int p = o >> 7, ci = o & 127;
    float s = obs[ci];
    const float* av = &ao[p*64];
    #pragma unroll 8
    for (int d = 0; d < 64; d++) s += owt[d*128+ci]*av[d];
    gf2[o] = s;
  }
  __syncthreads();
  for (int o = tid; o < 512; o += 256) {
    int p = o >> 5, co = o & 31;
    float s = g1bs[co];
    const float* gv = &gf2[p*128];
    #pragma unroll 8
    for (int c = 0; c < 128; c++) s += g1wt[c*32+co]*gv[c];
    hb[o] = fmaxf(s, 0.f);
  }
  __syncthreads();
  for (int o = tid; o < 2048; o += 256) {
    int p = o >> 7, ci = o & 127;
    float s = g2bs[ci];
    const float* hv = &hb[p*32];
    #pragma unroll
    for (int c = 0; c < 32; c++) s += g2wt[c*128+ci]*hv[c];
    swt[ci*16 + p] = 1.f/(1.f + __expf(-s));
  }
  __syncthreads();
  for (int o = tid; o < 2048; o += 256) {
    int ci = o >> 4, pp = o & 15;
    g_SW[((size_t)b*128+ci)*HWN + p0 + pp] = swt[o];
  }
}

// ===================================================================
// Kernel 4: final gating (with bilinear resample of gates for x2..x4)
// ===================================================================
__device__ __forceinline__ float sample_sw(const float* __restrict__ plane, int y, int x, int OH) {
  float fy = (float)y * 63.0f / (float)(OH-1);
  float fx = (float)x * 63.0f / (float)(OH-1);
  int y0 = (int)fy; if (y0 > 63) y0 = 63;
  int x0 = (int)fx; if (x0 > 63) x0 = 63;
  int y1 = min(y0+1, 63), x1 = min(x0+1, 63);
  float wy = fy - (float)y0, wx = fx - (float)x0;
  float a = plane[y0*64+x0], bv = plane[y0*64+x1];
  float c = plane[y1*64+x0], d = plane[y1*64+x1];
  return (a*(1.f-wx)+bv*wx)*(1.f-wy) + (c*(1.f-wx)+d*wx)*wy;
}

__global__ void gate_kernel(const float* __restrict__ x1, const float* __restrict__ x2,
                            const float* __restrict__ x3, const float* __restrict__ x4,
                            float* __restrict__ out) {
  int idx = blockIdx.x*256 + threadIdx.x;
  const int N1 = BB*32*4096, N2 = BB*32*1024, N3 = BB*32*256, N4 = BB*32*64;
  if (idx < N1) {
    int b = idx >> 17, c = (idx >> 12) & 31, p = idx & 4095;
    out[idx] = x1[idx]*(1.f + g_SW[((size_t)b*128 + c)*HWN + p]);
  } else if (idx < N1+N2) {
    int i = idx - N1;
    int b = i >> 15, c = (i >> 10) & 31, y = (i >> 5) & 31, x = i & 31;
    const float* plane = g_SW + ((size_t)b*128 + 32 + c)*HWN;
    out[idx] = x2[i]*(1.f + sample_sw(plane, y, x, 32));
  } else if (idx < N1+N2+N3) {
    int i = idx - N1 - N2;
    int b = i >> 13, c = (i >> 8) & 31, y = (i >> 4) & 15, x = i & 15;
    const float* plane = g_SW + ((size_t)b*128 + 64 + c)*HWN;
    out[idx] = x3[i]*(1.f + sample_sw(plane, y, x, 16));
  } else if (idx < N1+N2+N3+N4) {
    int i = idx - N1 - N2 - N3;
    int b = i >> 11, c = (i >> 6) & 31, y = (i >> 3) & 7, x = i & 7;
    const float* plane = g_SW + ((size_t)b*128 + 96 + c)*HWN;
    out[idx] = x4[i]*(1.f + sample_sw(plane, y, x, 8));
  }
}

// ===================================================================
extern "C" void kernel_launch(void* const* d_in, const int* in_sizes, int n_in,
                              void* d_out, int out_size) {
  const float* x1  = (const float*)d_in[0];
  const float* x2  = (const float*)d_in[1];
  const float* x3  = (const float*)d_in[2];
  const float* x4  = (const float*)d_in[3];
  const float* qw  = (const float*)d_in[4];
  const float* qb  = (const float*)d_in[5];
  const float* kw  = (const float*)d_in[6];
  const float* kb  = (const float*)d_in[7];
  const float* vw  = (const float*)d_in[8];
  const float* vb  = (const float*)d_in[9];
  const float* ow_ = (const float*)d_in[10];
  const float* ob  = (const float*)d_in[11];
  const float* g1w = (const float*)d_in[12];
  const float* g1b = (const float*)d_in[13];
  const float* g2w = (const float*)d_in[14];
  const float* g2b = (const float*)d_in[15];
  float* out = (float*)d_out;

  const int QKV_SMEM  = (128*192 + 128*68 + 192 + 192*65) * 4;  // 183808 B
  const int ATTN_SMEM = STAGEF*2*4;                             // 71680 B
  const int PROJ_SMEM = (8192+4096+4096+128+32+128+1024+2048+512+2048) * 4; // 89216 B

  cudaFuncSetAttribute(qkv_kernel,  cudaFuncAttributeMaxDynamicSharedMemorySize, QKV_SMEM);
  cudaFuncSetAttribute(attn_kernel, cudaFuncAttributeMaxDynamicSharedMemorySize, ATTN_SMEM);
  cudaFuncSetAttribute(proj_kernel, cudaFuncAttributeMaxDynamicSharedMemorySize, PROJ_SMEM);

  qkv_kernel <<<dim3(64, BB),  256, QKV_SMEM >>>(x1, x2, x3, x4, qw, qb, kw, kb, vw, vb);
  attn_kernel<<<dim3(32, BB),  256, ATTN_SMEM>>>();
  proj_kernel<<<dim3(256, BB), 256, PROJ_SMEM>>>(ow_, ob, g1w, g1b, g2w, g2b);

  const int TOTAL = BB*32*(4096 + 1024 + 256 + 64);  // 1392640
  gate_kernel<<<(TOTAL + 255)/256, 256>>>(x1, x2, x3, x4, out);
}

// round 3
// speedup vs baseline: 3.7245x; 1.4907x over previous
#include <cuda_runtime.h>
#include <cuda_bf16.h>
#include <math.h>
#include <stdint.h>

#define BB 8
#define HWN 4096

// -------- scratch (allocation-free rule: __device__ globals) --------
__device__ __nv_bfloat16 g_Qb[BB*HWN*64];   // [b][p][ci]
__device__ __nv_bfloat16 g_Kb[BB*HWN*64];   // [b][p][ci]
__device__ __nv_bfloat16 g_Vb[BB*64*HWN];   // [b][ci][p]  (transposed)
__device__ float g_AO[BB*HWN*64];           // attention output [b][p][d]
__device__ float g_SW[BB*128*HWN];          // sigmoid gates [b][ci][p]

__device__ __forceinline__ uint32_t pack_bf16x2(float lo, float hi) {
  uint32_t r;
  asm("cvt.rn.bf16x2.f32 %0, %1, %2;" : "=r"(r) : "f"(hi), "f"(lo));
  return r;
}

// ===================================================================
// Kernel 1: fused gf-build (upsample+concat) + QKV 1x1 convs
// grid (64 rows, B), 256 threads
// ===================================================================
__global__ void qkv_kernel(const float* __restrict__ x1, const float* __restrict__ x2,
                           const float* __restrict__ x3, const float* __restrict__ x4,
                           const float* __restrict__ qw, const float* __restrict__ qb,
                           const float* __restrict__ kw, const float* __restrict__ kb,
                           const float* __restrict__ vw, const float* __restrict__ vb) {
  extern __shared__ float sh[];
  float* wst  = sh;                    // [128][192] transposed weights (q|k|v)
  float* gfs  = wst + 128*192;         // [128][68]  channel-major gf row tile
  float* bias = gfs + 128*68;          // [192]
  float* outs = bias + 192;            // [192][65]  output staging (padded)
  const int b = blockIdx.y, y = blockIdx.x, tid = threadIdx.x;

  for (int i = tid; i < 64*128; i += 256) {
    int ci = i >> 7, c = i & 127;
    wst[c*192 + ci]       = qw[i];
    wst[c*192 + 64 + ci]  = kw[i];
    wst[c*192 + 128 + ci] = vw[i];
  }
  for (int i = tid; i < 192; i += 256)
    bias[i] = (i < 64) ? qb[i] : (i < 128 ? kb[i-64] : vb[i-128]);

  for (int i = tid; i < 32*64; i += 256) {
    int c = i >> 6, x = i & 63;
    gfs[c*68 + x] = x1[((b*32 + c)*64 + y)*64 + x];
  }
  const float* srcs[3] = {x2, x3, x4};
  const int    Hs[3]   = {32, 16, 8};
  #pragma unroll
  for (int lvl = 0; lvl < 3; lvl++) {
    const int H = Hs[lvl];
    const float* src = srcs[lvl];
    float fy = (float)y * (float)(H-1) / 63.0f;
    int y0 = (int)fy; if (y0 > H-1) y0 = H-1;
    int y1i = min(y0+1, H-1);
    float wy = fy - (float)y0;
    for (int i = tid; i < 32*64; i += 256) {
      int c = i >> 6, x = i & 63;
      float fx = (float)x * (float)(H-1) / 63.0f;
      int x0 = (int)fx; if (x0 > H-1) x0 = H-1;
      int x1i = min(x0+1, H-1);
      float wx = fx - (float)x0;
      const float* r0 = src + ((b*32 + c)*H + y0)*H;
      const float* r1 = src + ((b*32 + c)*H + y1i)*H;
      float top = r0[x0]*(1.f-wx) + r0[x1i]*wx;
      float bot = r1[x0]*(1.f-wx) + r1[x1i]*wx;
      gfs[(32*(lvl+1) + c)*68 + x] = top*(1.f-wy) + bot*wy;
    }
  }
  __syncthreads();

  const int tx = tid & 15, ty = tid >> 4;
  float acc[12][4];
  #pragma unroll
  for (int i = 0; i < 12; i++) { acc[i][0]=acc[i][1]=acc[i][2]=acc[i][3]=0.f; }
  for (int c = 0; c < 128; c++) {
    float4 g = *(const float4*)&gfs[c*68 + tx*4];
    const float* wr = &wst[c*192 + ty*12];
    float4 w0 = *(const float4*)&wr[0];
    float4 w1 = *(const float4*)&wr[4];
    float4 w2 = *(const float4*)&wr[8];
    float wv[12] = {w0.x,w0.y,w0.z,w0.w, w1.x,w1.y,w1.z,w1.w, w2.x,w2.y,w2.z,w2.w};
    #pragma unroll
    for (int i = 0; i < 12; i++) {
      acc[i][0] += wv[i]*g.x; acc[i][1] += wv[i]*g.y;
      acc[i][2] += wv[i]*g.z; acc[i][3] += wv[i]*g.w;
    }
  }
  #pragma unroll
  for (int i = 0; i < 12; i++) {
    int row = ty*12 + i;
    float bbv = bias[row];
    #pragma unroll
    for (int j = 0; j < 4; j++)
      outs[row*65 + tx*4 + j] = acc[i][j] + bbv;
  }
  __syncthreads();

  // writeout: Q,K as bf16 [p][64]; V transposed bf16 [d][p]
  const int pbase = b*HWN + y*64;
  uint32_t* Qu = (uint32_t*)g_Qb + (size_t)pbase*32;
  uint32_t* Ku = (uint32_t*)g_Kb + (size_t)pbase*32;
  for (int i = tid; i < 2048; i += 256) {
    int p = i >> 5, c2 = i & 31;
    Qu[p*32 + c2] = pack_bf16x2(outs[(2*c2)*65 + p],     outs[(2*c2+1)*65 + p]);
    Ku[p*32 + c2] = pack_bf16x2(outs[(64+2*c2)*65 + p],  outs[(65+2*c2)*65 + p]);
  }
  uint32_t* Vu = (uint32_t*)g_Vb;
  for (int i = tid; i < 2048; i += 256) {
    int d = i >> 5, px = i & 31;
    const float* vr = &outs[(128+d)*65];
    Vu[((size_t)(b*64+d)*HWN + y*64)/2 + px] = pack_bf16x2(vr[2*px], vr[2*px+1]);
  }
}

// ===================================================================
// Kernel 2: bf16 tensor-core flash attention, d=64, seq=4096
// grid (32 q-tiles of 128, B), 256 threads (8 warps x 16 rows), 2 CTA/SM
// ===================================================================
#define KVW 36                       // row stride in u32 (72 bf16)
#define KBYTES (64*KVW*4)            // 9216 B per K tile
#define STAGE_BYTES (2*KBYTES)       // K + V = 18432 B

__device__ __forceinline__ void cp_async16(uint32_t smem_dst, const void* gsrc) {
  asm volatile("cp.async.ca.shared.global [%0], [%1], 16;\n"
               :: "r"(smem_dst), "l"(gsrc));
}

__device__ __forceinline__ void mma_bf16(float d[4], const uint32_t a[4],
                                         uint32_t b0, uint32_t b1) {
  asm volatile("mma.sync.aligned.m16n8k16.row.col.f32.bf16.bf16.f32 "
               "{%0,%1,%2,%3}, {%4,%5,%6,%7}, {%8,%9}, {%0,%1,%2,%3};"
               : "+f"(d[0]), "+f"(d[1]), "+f"(d[2]), "+f"(d[3])
               : "r"(a[0]), "r"(a[1]), "r"(a[2]), "r"(a[3]), "r"(b0), "r"(b1));
}

__device__ __forceinline__ void prefetch_kv(uint32_t sbase, int b, int jt, int stage, int tid) {
  uint32_t st = sbase + (uint32_t)stage * STAGE_BYTES;
  const __nv_bfloat16* Ksrc = g_Kb + ((size_t)b*HWN + jt*64)*64;
  const __nv_bfloat16* Vsrc = g_Vb + (size_t)b*64*HWN + jt*64;
  #pragma unroll
  for (int k = 0; k < 4; k++) {
    int i = tid + k*256;             // 0..1023
    if (i < 512) {                   // K tile: 64 rows x 128B
      int r = i >> 3, c = i & 7;
      cp_async16(st + (uint32_t)(r*KVW*4 + c*16), Ksrc + r*64 + c*8);
    } else {                         // V tile (transposed): 64 d-rows x 128B
      int j = i - 512, r = j >> 3, c = j & 7;
      cp_async16(st + KBYTES + (uint32_t)(r*KVW*4 + c*16), Vsrc + (size_t)r*HWN + c*8);
    }
  }
}

__global__ void __launch_bounds__(256, 2) attn_kernel() {
  extern __shared__ float sh[];
  uint32_t sbase = (uint32_t)__cvta_generic_to_shared(sh);
  const int b = blockIdx.y, m0 = blockIdx.x*128;
  const int tid = threadIdx.x, w = tid >> 5, lane = tid & 31;
  const int g = lane >> 2, t = lane & 3;

  // Q fragments (bf16x2 words), resident in registers
  const uint32_t* Qu = (const uint32_t*)g_Qb + ((size_t)b*HWN + m0 + w*16)*32;
  uint32_t qa[4][4];
  #pragma unroll
  for (int kt = 0; kt < 4; kt++) {
    qa[kt][0] = Qu[ g   *32 + kt*8 + t    ];
    qa[kt][1] = Qu[(g+8)*32 + kt*8 + t    ];
    qa[kt][2] = Qu[ g   *32 + kt*8 + t + 4];
    qa[kt][3] = Qu[(g+8)*32 + kt*8 + t + 4];
  }

  float m0r = -1e30f, m1r = -1e30f, l0 = 0.f, l1 = 0.f;
  float o[8][4] = {};

  prefetch_kv(sbase, b, 0, 0, tid);
  asm volatile("cp.async.commit_group;\n" ::: "memory");

  for (int jt = 0; jt < 64; jt++) {
    if (jt + 1 < 64) {
      prefetch_kv(sbase, b, jt+1, (jt+1)&1, tid);
      asm volatile("cp.async.commit_group;\n" ::: "memory");
      asm volatile("cp.async.wait_group 1;\n" ::: "memory");
    } else {
      asm volatile("cp.async.wait_group 0;\n" ::: "memory");
    }
    __syncthreads();

    const uint32_t* Ku32 = (const uint32_t*)sh + (jt&1)*(STAGE_BYTES/4);
    const uint32_t* Vu32 = Ku32 + KBYTES/4;

    // ---- S = Q K^T (16x64 per warp) ----
    float s[8][4] = {};
    #pragma unroll
    for (int kt = 0; kt < 4; kt++) {
      #pragma unroll
      for (int nt = 0; nt < 8; nt++) {
        uint32_t b0 = Ku32[(nt*8 + g)*KVW + kt*8 + t];
        uint32_t b1 = Ku32[(nt*8 + g)*KVW + kt*8 + t + 4];
        mma_bf16(s[nt], qa[kt], b0, b1);
      }
    }

    // ---- online softmax (rows g and g+8) ----
    float rmax0 = -1e30f, rmax1 = -1e30f;
    #pragma unroll
    for (int nt = 0; nt < 8; nt++) {
      rmax0 = fmaxf(rmax0, fmaxf(s[nt][0], s[nt][1]));
      rmax1 = fmaxf(rmax1, fmaxf(s[nt][2], s[nt][3]));
    }
    rmax0 = fmaxf(rmax0, __shfl_xor_sync(0xffffffffu, rmax0, 1));
    rmax0 = fmaxf(rmax0, __shfl_xor_sync(0xffffffffu, rmax0, 2));
    rmax1 = fmaxf(rmax1, __shfl_xor_sync(0xffffffffu, rmax1, 1));
    rmax1 = fmaxf(rmax1, __shfl_xor_sync(0xffffffffu, rmax1, 2));
    float mn0 = fmaxf(m0r, rmax0), mn1 = fmaxf(m1r, rmax1);
    float c0 = __expf(m0r - mn0), c1 = __expf(m1r - mn1);
    m0r = mn0; m1r = mn1;
    float rs0 = 0.f, rs1 = 0.f;
    #pragma unroll
    for (int nt = 0; nt < 8; nt++) {
      s[nt][0] = __expf(s[nt][0] - mn0);
      s[nt][1] = __expf(s[nt][1] - mn0);
      s[nt][2] = __expf(s[nt][2] - mn1);
      s[nt][3] = __expf(s[nt][3] - mn1);
      rs0 += s[nt][0] + s[nt][1];
      rs1 += s[nt][2] + s[nt][3];
    }
    rs0 += __shfl_xor_sync(0xffffffffu, rs0, 1);
    rs0 += __shfl_xor_sync(0xffffffffu, rs0, 2);
    rs1 += __shfl_xor_sync(0xffffffffu, rs1, 1);
    rs1 += __shfl_xor_sync(0xffffffffu, rs1, 2);
    l0 = l0*c0 + rs0;  l1 = l1*c1 + rs1;
    #pragma unroll
    for (int nt = 0; nt < 8; nt++) {
      o[nt][0] *= c0; o[nt][1] *= c0; o[nt][2] *= c1; o[nt][3] *= c1;
    }

    // ---- O += P V : C-frag layout == A-frag layout for f16 mma (no shuffles) ----
    #pragma unroll
    for (int kt = 0; kt < 4; kt++) {
      uint32_t pa[4];
      pa[0] = pack_bf16x2(s[2*kt  ][0], s[2*kt  ][1]);
      pa[1] = pack_bf16x2(s[2*kt  ][2], s[2*kt  ][3]);
      pa[2] = pack_bf16x2(s[2*kt+1][0], s[2*kt+1][1]);
      pa[3] = pack_bf16x2(s[2*kt+1][2], s[2*kt+1][3]);
      #pragma unroll
      for (int nt = 0; nt < 8; nt++) {
        uint32_t b0 = Vu32[(nt*8 + g)*KVW + kt*8 + t];
        uint32_t b1 = Vu32[(nt*8 + g)*KVW + kt*8 + t + 4];
        mma_bf16(o[nt], pa, b0, b1);
      }
    }
    __syncthreads();   // all reads of this stage done before refill
  }

  float* AO = g_AO + ((size_t)b*HWN + m0 + w*16)*64;
  float i0 = 1.f / l0, i1 = 1.f / l1;
  #pragma unroll
  for (int nt = 0; nt < 8; nt++) {
    *(float2*)&AO[ g   *64 + nt*8 + 2*t] = make_float2(o[nt][0]*i0, o[nt][1]*i0);
    *(float2*)&AO[(g+8)*64 + nt*8 + 2*t] = make_float2(o[nt][2]*i1, o[nt][3]*i1);
  }
}

// ===================================================================
// Kernel 3: out-proj + gate MLP + sigmoid  (attn_out -> g_SW)
// grid (128 pos-tiles of 32, B), 256 threads
// ===================================================================
__global__ void proj_kernel(const float* __restrict__ ow_, const float* __restrict__ ob,
                            const float* __restrict__ g1w, const float* __restrict__ g1b,
                            const float* __restrict__ g2w, const float* __restrict__ g2b) {
  extern __shared__ float sh[];
  float* owt  = sh;              // [64][128]
  float* g1wt = owt + 8192;      // [128][32]
  float* g2wt = g1wt + 4096;     // [32][128]
  float* obs  = g2wt + 4096;     // 128
  float* g1bs = obs + 128;       // 32
  float* g2bs = g1bs + 32;       // 128
  float* ao   = g2bs + 128;      // [32][64]
  float* gf2  = ao + 2048;       // [32][128]
  float* hb   = gf2 + 4096;      // [32][32]
  float* swt  = hb + 1024;       // [128][32]
  const int b = blockIdx.y, p0 = blockIdx.x*32, tid = threadIdx.x;

  for (int i = tid; i < 8192; i += 256) { int ci = i>>6, d = i&63;  owt [d*128+ci] = ow_[i]; }
  for (int i = tid; i < 4096; i += 256) { int co = i>>7, c = i&127; g1wt[c*32 +co] = g1w[i]; }
  for (int i = tid; i < 4096; i += 256) { int ci = i>>5, c = i&31;  g2wt[c*128+ci] = g2w[i]; }
  for (int i = tid; i < 128;  i += 256) obs[i]  = ob[i];
  for (int i = tid; i < 32;   i += 256) g1bs[i] = g1b[i];
  for (int i = tid; i < 128;  i += 256) g2bs[i] = g2b[i];
  const float* AOg = g_AO + ((size_t)b*HWN + p0)*64;
  for (int i = tid; i < 2048; i += 256) ao[i] = AOg[i];
  __syncthreads();

  for (int o = tid; o < 4096; o += 256) {
    int p = o >> 7, ci = o & 127;
    float s = obs[ci];
    const float* av = &ao[p*64];
    #pragma unroll 8
    for (int d = 0; d < 64; d++) s += owt[d*128+ci]*av[d];
    gf2[o] = s;
  }
  __syncthreads();
  for (int o = tid; o < 1024; o += 256) {
    int p = o >> 5, co = o & 31;
    float s = g1bs[co];
    const float* gv = &gf2[p*128];
    #pragma unroll 8
    for (int c = 0; c < 128; c++) s += g1wt[c*32+co]*gv[c];
    hb[o] = fmaxf(s, 0.f);
  }
  __syncthreads();
  for (int o = tid; o < 4096; o += 256) {
    int p = o >> 7, ci = o & 127;
    float s = g2bs[ci];
    const float* hv = &hb[p*32];
    #pragma unroll
    for (int c = 0; c < 32; c++) s += g2wt[c*128+ci]*hv[c];
    swt[ci*32 + p] = 1.f/(1.f + __expf(-s));
  }
  __syncthreads();
  for (int o = tid; o < 4096; o += 256) {
    int ci = o >> 5, pp = o & 31;
    g_SW[((size_t)b*128+ci)*HWN + p0 + pp] = swt[o];
  }
}

// ===================================================================
// Kernel 4: final gating (with bilinear resample of gates for x2..x4)
// ===================================================================
__device__ __forceinline__ float sample_sw(const float* __restrict__ plane, int y, int x, int OH) {
  float fy = (float)y * 63.0f / (float)(OH-1);
  float fx = (float)x * 63.0f / (float)(OH-1);
  int y0 = (int)fy; if (y0 > 63) y0 = 63;
  int x0 = (int)fx; if (x0 > 63) x0 = 63;
  int y1 = min(y0+1, 63), x1 = min(x0+1, 63);
  float wy = fy - (float)y0, wx = fx - (float)x0;
  float a = plane[y0*64+x0], bv = plane[y0*64+x1];
  float c = plane[y1*64+x0], d = plane[y1*64+x1];
  return (a*(1.f-wx)+bv*wx)*(1.f-wy) + (c*(1.f-wx)+d*wx)*wy;
}

__global__ void gate_kernel(const float* __restrict__ x1, const float* __restrict__ x2,
                            const float* __restrict__ x3, const float* __restrict__ x4,
                            float* __restrict__ out) {
  int idx = blockIdx.x*256 + threadIdx.x;
  const int N1 = BB*32*4096, N2 = BB*32*1024, N3 = BB*32*256, N4 = BB*32*64;
  if (idx < N1) {
    int b = idx >> 17, c = (idx >> 12) & 31, p = idx & 4095;
    out[idx] = x1[idx]*(1.f + g_SW[((size_t)b*128 + c)*HWN + p]);
  } else if (idx < N1+N2) {
    int i = idx - N1;
    int b = i >> 15, c = (i >> 10) & 31, y = (i >> 5) & 31, x = i & 31;
    const float* plane = g_SW + ((size_t)b*128 + 32 + c)*HWN;
    out[idx] = x2[i]*(1.f + sample_sw(plane, y, x, 32));
  } else if (idx < N1+N2+N3) {
    int i = idx - N1 - N2;
    int b = i >> 13, c = (i >> 8) & 31, y = (i >> 4) & 15, x = i & 15;
    const float* plane = g_SW + ((size_t)b*128 + 64 + c)*HWN;
    out[idx] = x3[i]*(1.f + sample_sw(plane, y, x, 16));
  } else if (idx < N1+N2+N3+N4) {
    int i = idx - N1 - N2 - N3;
    int b = i >> 11, c = (i >> 6) & 31, y = (i >> 3) & 7, x = i & 7;
    const float* plane = g_SW + ((size_t)b*128 + 96 + c)*HWN;
    out[idx] = x4[i]*(1.f + sample_sw(plane, y, x, 8));
  }
}

// ===================================================================
extern "C" void kernel_launch(void* const* d_in, const int* in_sizes, int n_in,
                              void* d_out, int out_size) {
  const float* x1  = (const float*)d_in[0];
  const float* x2  = (const float*)d_in[1];
  const float* x3  = (const float*)d_in[2];
  const float* x4  = (const float*)d_in[3];
  const float* qw  = (const float*)d_in[4];
  const float* qb  = (const float*)d_in[5];
  const float* kw  = (const float*)d_in[6];
  const float* kb  = (const float*)d_in[7];
  const float* vw  = (const float*)d_in[8];
  const float* vb  = (const float*)d_in[9];
  const float* ow_ = (const float*)d_in[10];
  const float* ob  = (const float*)d_in[11];
  const float* g1w = (const float*)d_in[12];
  const float* g1b = (const float*)d_in[13];
  const float* g2w = (const float*)d_in[14];
  const float* g2b = (const float*)d_in[15];
  float* out = (float*)d_out;

  const int QKV_SMEM  = (128*192 + 128*68 + 192 + 192*65) * 4;  // 183808 B
  const int ATTN_SMEM = STAGE_BYTES*2;                          // 36864 B
  const int PROJ_SMEM = (8192+4096+4096+128+32+128+2048+4096+1024+4096) * 4; // 111360 B

  cudaFuncSetAttribute(qkv_kernel,  cudaFuncAttributeMaxDynamicSharedMemorySize, QKV_SMEM);
  cudaFuncSetAttribute(attn_kernel, cudaFuncAttributeMaxDynamicSharedMemorySize, ATTN_SMEM);
  cudaFuncSetAttribute(proj_kernel, cudaFuncAttributeMaxDynamicSharedMemorySize, PROJ_SMEM);

  qkv_kernel <<<dim3(64, BB),  256, QKV_SMEM >>>(x1, x2, x3, x4, qw, qb, kw, kb, vw, vb);
  attn_kernel<<<dim3(32, BB),  256, ATTN_SMEM>>>();
  proj_kernel<<<dim3(128, BB), 256, PROJ_SMEM>>>(ow_, ob, g1w, g1b, g2w, g2b);

  const int TOTAL = BB*32*(4096 + 1024 + 256 + 64);  // 1392640
  gate_kernel<<<(TOTAL + 255)/256, 256>>>(x1, x2, x3, x4, out);
}